// round 8
// baseline (speedup 1.0000x reference)
#include <cuda_runtime.h>
#include <cuda_bf16.h>
#include <cstdint>
#include <cstddef>

// Problem constants
#define BB   4
#define TT   2048
#define DM   1024
#define DI   2048
#define DX   4096
#define MROWS (BB*TT)   // 8192

// GEMM tiling
#define BKC   32
#define PITCH 40                       // bf16 per smem row (32 + 8 pad)
#define TILE_BYTES (128*PITCH*2)       // 10240
#define STAGE_BYTES (4*TILE_BYTES)     // Ah,Al,Bh,Bl
#define NSTAGE 4
#define GEMM_SMEM (NSTAGE*STAGE_BYTES + 1024)

// Scan config
#define SCP  5
#define SCT  512
#define SCAN_SMEM ((SCP*4*DI + DI + 32)*4)

// ---------------- scratch ----------------------------------------------------
__device__ __nv_bfloat16 g_xh [(size_t)MROWS * DM],  g_xl [(size_t)MROWS * DM];
__device__ __nv_bfloat16 g_winh[(size_t)DX * DM],    g_winl[(size_t)DX * DM];
__device__ __nv_bfloat16 g_wlh[(size_t)DI * DI],     g_wll[(size_t)DI * DI];
__device__ __nv_bfloat16 g_wvh[(size_t)DI * DI],     g_wvl[(size_t)DI * DI];
__device__ __nv_bfloat16 g_woh[(size_t)DM * DI],     g_wol[(size_t)DM * DI];
__device__ float         g_xi [(size_t)MROWS * DI];
__device__ __nv_bfloat16 g_xih[(size_t)MROWS * DI],  g_xil[(size_t)MROWS * DI];
__device__ float         g_sz [(size_t)MROWS * DI];
__device__ float         g_lam[(size_t)MROWS * DI];
__device__ float         g_v  [(size_t)MROWS * DI];
__device__ __nv_bfloat16 g_gh [(size_t)MROWS * DI],  g_gl [(size_t)MROWS * DI];
__device__ float         g_fcolA[DI];

// ---------------- helpers ------------------------------------------------------
__device__ __forceinline__ uint32_t smem_u32(const void* p) {
    uint32_t a;
    asm("{ .reg .u64 t; cvta.to.shared.u64 t, %1; cvt.u32.u64 %0, t; }" : "=r"(a) : "l"(p));
    return a;
}
__device__ __forceinline__ void cp16(uint32_t dst, const void* src) {
    asm volatile("cp.async.cg.shared.global [%0], [%1], 16;" :: "r"(dst), "l"(src));
}
#define CP_COMMIT() asm volatile("cp.async.commit_group;" ::: "memory")
#define CP_WAIT(n)  asm volatile("cp.async.wait_group %0;" :: "n"(n) : "memory")

__device__ __forceinline__ void mma_bf16(float* c, const uint32_t* a, const uint32_t* b) {
    asm volatile(
        "mma.sync.aligned.m16n8k16.row.col.f32.bf16.bf16.f32 "
        "{%0,%1,%2,%3}, {%4,%5,%6,%7}, {%8,%9}, {%0,%1,%2,%3};"
        : "+f"(c[0]), "+f"(c[1]), "+f"(c[2]), "+f"(c[3])
        : "r"(a[0]), "r"(a[1]), "r"(a[2]), "r"(a[3]), "r"(b[0]), "r"(b[1]));
}
#define LDSM_X4(r, addr) \
    asm volatile("ldmatrix.sync.aligned.m8n8.x4.shared.b16 {%0,%1,%2,%3}, [%4];" \
        : "=r"((r)[0]), "=r"((r)[1]), "=r"((r)[2]), "=r"((r)[3]) : "r"(addr))

__device__ __forceinline__ void split2(float a, float b, uint32_t& hv, uint32_t& lv) {
    __nv_bfloat162 h = __float22bfloat162_rn(make_float2(a, b));
    float2 hf = __bfloat1622float2(h);
    __nv_bfloat162 l = __float22bfloat162_rn(make_float2(a - hf.x, b - hf.y));
    hv = *(uint32_t*)&h; lv = *(uint32_t*)&l;
}

// ---------------- mega pre-pass: all splits + fcol in one launch -----------------
__global__ __launch_bounds__(256) void mega_pre(
    const float* __restrict__ x,    __nv_bfloat16* __restrict__ xh,   __nv_bfloat16* __restrict__ xl,
    const float* __restrict__ Win,  __nv_bfloat16* __restrict__ winh, __nv_bfloat16* __restrict__ winl,
    const float* __restrict__ Wl,   __nv_bfloat16* __restrict__ wlh,  __nv_bfloat16* __restrict__ wll,
    const float* __restrict__ Wv,   __nv_bfloat16* __restrict__ wvh,  __nv_bfloat16* __restrict__ wvl,
    const float* __restrict__ Wout, __nv_bfloat16* __restrict__ woh,  __nv_bfloat16* __restrict__ wol,
    const float* __restrict__ omega, float* __restrict__ fcol)
{
    const int seg = blockIdx.y;
    const int tid = threadIdx.x;
    if (seg == 5) {
        if (blockIdx.x == 0) {
            for (int i = tid; i < DI; i += 256)
                fcol[i] = -8.0f * log1pf(__expf(omega[i]));
        }
        return;
    }
    const float* src; __nv_bfloat16 *hi, *lo; int n;
    switch (seg) {
        case 0: src = x;    hi = xh;   lo = xl;   n = MROWS * DM; break;
        case 1: src = Win;  hi = winh; lo = winl; n = DX * DM;    break;
        case 2: src = Wl;   hi = wlh;  lo = wll;  n = DI * DI;    break;
        case 3: src = Wv;   hi = wvh;  lo = wvl;  n = DI * DI;    break;
        default:src = Wout; hi = woh;  lo = wol;  n = DM * DI;    break;
    }
    const int i = (blockIdx.x * 256 + tid) * 4;
    if (i >= n) return;
    float4 f = *(const float4*)(src + i);
    uint32_t h0, l0, h1, l1;
    split2(f.x, f.y, h0, l0);
    split2(f.z, f.w, h1, l1);
    *(uint2*)(hi + i) = make_uint2(h0, h1);
    *(uint2*)(lo + i) = make_uint2(l0, l1);
}

// ---------------- NT GEMM on pre-split operands ---------------------------------
// per blockIdx.z: selects (B,bias,C,mode). mode 0: +bias; 1: lambda epi; 2: xi/silu(z)
__global__ __launch_bounds__(256, 1) void gemm_ps(
    const __nv_bfloat16* __restrict__ Ahg, const __nv_bfloat16* __restrict__ Alg, int lda,
    const __nv_bfloat16* __restrict__ Bhg, const __nv_bfloat16* __restrict__ Blg,
    const __nv_bfloat16* __restrict__ Bhg2, const __nv_bfloat16* __restrict__ Blg2, int ldb,
    int K,
    float* __restrict__ C0, float* __restrict__ C1, int ldc,
    const float* __restrict__ bias, const float* __restrict__ bias2,
    const float* __restrict__ fcolg,
    __nv_bfloat16* __restrict__ Chi, __nv_bfloat16* __restrict__ Clo,
    float* __restrict__ Csz, int mode, int mode2)
{
    extern __shared__ char smraw[];
    const uint32_t smem_u = smem_u32(smraw);
    float* bias_s = (float*)(smraw + NSTAGE * STAGE_BYTES);
    float* fcol_s = bias_s + 128;

    const int tid = threadIdx.x;
    const int wid = tid >> 5, lane = tid & 31;
    const int g = lane >> 2, tq = lane & 3;
    const int wm = wid >> 2, wn = wid & 3;
    const int rowBase = blockIdx.y * 128;
    const int colBase = blockIdx.x * 128;

    const __nv_bfloat16* Bh_ = Bhg; const __nv_bfloat16* Bl_ = Blg;
    const float* biasp = bias; float* Cp = C0; int md = mode;
    if (blockIdx.z == 1) { Bh_ = Bhg2; Bl_ = Blg2; biasp = bias2; Cp = C1; md = mode2; }

    if (tid < 128) {
        int c = colBase + tid;
        bias_s[tid] = biasp ? biasp[c] : 0.f;
        fcol_s[tid] = (md == 1) ? fcolg[c] : 0.f;
    }

    const int nc = K / BKC;
    const int u0 = tid, u1 = tid + 256;

    auto fill = [&](int c) {
        const uint32_t sb = smem_u + (uint32_t)(c % NSTAGE) * STAGE_BYTES;
        #pragma unroll
        for (int i = 0; i < 2; i++) {
            const int unit = i ? u1 : u0;
            const int row = unit >> 2, seg = unit & 3;
            const uint32_t so = (uint32_t)(row * PITCH + seg * 8) * 2;
            const size_t ga = (size_t)(rowBase + row) * lda + c * BKC + seg * 8;
            const size_t gb = (size_t)(colBase + row) * ldb + c * BKC + seg * 8;
            cp16(sb + 0 * TILE_BYTES + so, Ahg + ga);
            cp16(sb + 1 * TILE_BYTES + so, Alg + ga);
            cp16(sb + 2 * TILE_BYTES + so, Bh_ + gb);
            cp16(sb + 3 * TILE_BYTES + so, Bl_ + gb);
        }
        CP_COMMIT();
    };

    fill(0);
    fill(1);

    float acc[4][4][4];
    #pragma unroll
    for (int mt = 0; mt < 4; mt++)
        #pragma unroll
        for (int nt = 0; nt < 4; nt++)
            #pragma unroll
            for (int j = 0; j < 4; j++) acc[mt][nt][j] = 0.f;

    const int lr = lane & 15, lcq = (lane >> 4) << 3;

    for (int c = 0; c < nc; c++) {
        // canonical order: issue next fill, wait own groups thru G_c, THEN barrier
        // (barrier after wait makes all threads' G_c globally visible — fixes the
        //  round-7 cross-thread cp.async race)
        if (c + 2 < nc) fill(c + 2); else CP_COMMIT();
        CP_WAIT(2);
        __syncthreads();

        const uint32_t ub = smem_u + (uint32_t)(c % NSTAGE) * STAGE_BYTES;
        const uint32_t uAh = ub, uAl = ub + TILE_BYTES;
        const uint32_t uBh = ub + 2 * TILE_BYTES, uBl = ub + 3 * TILE_BYTES;

        #pragma unroll
        for (int kk = 0; kk < 2; kk++) {
            const int kc = kk * 16;
            uint32_t ah[4][4], al[4][4], bh[2][4], bl[2][4];
            #pragma unroll
            for (int mt = 0; mt < 4; mt++) {
                const uint32_t off = (uint32_t)(((wm * 64 + mt * 16 + lr) * PITCH + kc + lcq) * 2);
                LDSM_X4(ah[mt], uAh + off);
                LDSM_X4(al[mt], uAl + off);
            }
            #pragma unroll
            for (int p = 0; p < 2; p++) {
                const uint32_t off = (uint32_t)(((wn * 32 + p * 16 + lr) * PITCH + kc + lcq) * 2);
                LDSM_X4(bh[p], uBh + off);
                LDSM_X4(bl[p], uBl + off);
            }
            uint32_t bH[4][2] = {{bh[0][0], bh[0][2]}, {bh[0][1], bh[0][3]},
                                 {bh[1][0], bh[1][2]}, {bh[1][1], bh[1][3]}};
            uint32_t bL[4][2] = {{bl[0][0], bl[0][2]}, {bl[0][1], bl[0][3]},
                                 {bl[1][0], bl[1][2]}, {bl[1][1], bl[1][3]}};
            #pragma unroll
            for (int mt = 0; mt < 4; mt++)
                #pragma unroll
                for (int nt = 0; nt < 4; nt++)
                    mma_bf16(acc[mt][nt], ah[mt], bH[nt]);
            #pragma unroll
            for (int mt = 0; mt < 4; mt++)
                #pragma unroll
                for (int nt = 0; nt < 4; nt++)
                    mma_bf16(acc[mt][nt], ah[mt], bL[nt]);
            #pragma unroll
            for (int mt = 0; mt < 4; mt++)
                #pragma unroll
                for (int nt = 0; nt < 4; nt++)
                    mma_bf16(acc[mt][nt], al[mt], bH[nt]);
        }
    }

    // epilogue
    const bool isxi = (md == 2) && (colBase < DI);
    const bool isz  = (md == 2) && (colBase >= DI);
    #pragma unroll
    for (int mt = 0; mt < 4; mt++) {
        const int r0 = rowBase + wm * 64 + mt * 16 + g;
        #pragma unroll
        for (int nt = 0; nt < 4; nt++) {
            const int col = wn * 32 + nt * 8 + tq * 2;
            float v0 = acc[mt][nt][0] + bias_s[col];
            float v1 = acc[mt][nt][1] + bias_s[col + 1];
            float v2 = acc[mt][nt][2] + bias_s[col];
            float v3 = acc[mt][nt][3] + bias_s[col + 1];
            if (md == 1) {
                const float f0 = fcol_s[col], f1 = fcol_s[col + 1];
                v0 = __expf(f0 * __frcp_rn(1.0f + __expf(-v0)));
                v1 = __expf(f1 * __frcp_rn(1.0f + __expf(-v1)));
                v2 = __expf(f0 * __frcp_rn(1.0f + __expf(-v2)));
                v3 = __expf(f1 * __frcp_rn(1.0f + __expf(-v3)));
            }
            if (isz) {
                const int cc = colBase - DI + col;
                float s0 = v0 * __frcp_rn(1.0f + __expf(-v0));
                float s1 = v1 * __frcp_rn(1.0f + __expf(-v1));
                float s2 = v2 * __frcp_rn(1.0f + __expf(-v2));
                float s3 = v3 * __frcp_rn(1.0f + __expf(-v3));
                *(float2*)(Csz + (size_t)r0 * DI + cc)       = make_float2(s0, s1);
                *(float2*)(Csz + (size_t)(r0 + 8) * DI + cc) = make_float2(s2, s3);
            } else {
                const int cc = colBase + col;
                *(float2*)(Cp + (size_t)r0 * ldc + cc)       = make_float2(v0, v1);
                *(float2*)(Cp + (size_t)(r0 + 8) * ldc + cc) = make_float2(v2, v3);
                if (isxi) {
                    uint32_t h0, l0, h1, l1;
                    split2(v0, v1, h0, l0);
                    split2(v2, v3, h1, l1);
                    *(uint32_t*)(Chi + (size_t)r0 * DI + cc)       = h0;
                    *(uint32_t*)(Clo + (size_t)r0 * DI + cc)       = l0;
                    *(uint32_t*)(Chi + (size_t)(r0 + 8) * DI + cc) = h1;
                    *(uint32_t*)(Clo + (size_t)(r0 + 8) * DI + cc) = l1;
                }
            }
        }
    }
}

// ---------------- scan: fused 2/(v.v) + cp.async prefetch ring --------------------
__global__ __launch_bounds__(SCT, 1) void scan_kernel(
    const float* __restrict__ xi, const float* __restrict__ sz,
    const float* __restrict__ lam, const float* __restrict__ v,
    __nv_bfloat16* __restrict__ gh, __nv_bfloat16* __restrict__ gl)
{
    extern __shared__ float sms[];
    float* ring = sms;                       // [SCP][4][DI]
    float* svs  = sms + SCP * 4 * DI;        // [TT]
    float* part = svs + DI;                  // [2][16]
    const uint32_t ring_u = smem_u32(ring);

    const int b = blockIdx.x;
    const int tid = threadIdx.x;
    const int lane = tid & 31, wrp = tid >> 5;
    const int c0 = tid * 4;

    const float* xib  = xi  + (size_t)b * TT * DI;
    const float* szb  = sz  + (size_t)b * TT * DI;
    const float* lamb = lam + (size_t)b * TT * DI;
    const float* vb   = v   + (size_t)b * TT * DI;
    __nv_bfloat16* ghb = gh + (size_t)b * TT * DI;
    __nv_bfloat16* glb = gl + (size_t)b * TT * DI;

    // sv[t] = 2/(v_t . v_t), 16 warps x 128 rows each
    for (int r = wrp; r < TT; r += 16) {
        const float4* vr = (const float4*)(vb + (size_t)r * DI);
        float s = 0.f;
        #pragma unroll
        for (int i = 0; i < 16; i++) {
            float4 a = vr[lane + i * 32];
            s += a.x * a.x + a.y * a.y + a.z * a.z + a.w * a.w;
        }
        #pragma unroll
        for (int o = 16; o; o >>= 1) s += __shfl_xor_sync(0xffffffffu, s, o);
        if (lane == 0) svs[r] = 2.0f / s;
    }

    auto fill = [&](int t) {
        const int s = t % SCP;
        const uint32_t base = ring_u + (uint32_t)(s * 4 * DI) * 4 + (uint32_t)c0 * 4;
        const size_t o = (size_t)t * DI + c0;
        cp16(base + 0 * DI * 4, vb   + o);
        cp16(base + 1 * DI * 4, lamb + o);
        cp16(base + 2 * DI * 4, xib  + o);
        cp16(base + 3 * DI * 4, szb  + o);
        CP_COMMIT();
    };

    // h0 + g0
    float4 h = *(const float4*)(xib + c0);
    {
        float4 s0 = *(const float4*)(szb + c0);
        uint32_t h0, l0, h1, l1;
        split2(s0.x * h.x, s0.y * h.y, h0, l0);
        split2(s0.z * h.z, s0.w * h.w, h1, l1);
        *(uint2*)(ghb + c0) = make_uint2(h0, h1);
        *(uint2*)(glb + c0) = make_uint2(l0, l1);
    }

    #pragma unroll
    for (int t = 1; t < SCP; t++) fill(t);
    CP_WAIT(SCP - 2);
    __syncthreads();

    for (int t = 1; t < TT; t++) {
        const int s = t % SCP;
        const float* st_v = ring + (s * 4 + 0) * DI + c0;
        const float4 vt = *(const float4*)(st_v);
        const float4 lt = *(const float4*)(st_v + 1 * DI);
        const float4 xt = *(const float4*)(st_v + 2 * DI);
        const float4 zt = *(const float4*)(st_v + 3 * DI);

        float p = vt.x * h.x + vt.y * h.y + vt.z * h.z + vt.w * h.w;
        #pragma unroll
        for (int o = 16; o; o >>= 1) p += __shfl_xor_sync(0xffffffffu, p, o);
        if (lane == 0) part[((t & 1) << 4) + wrp] = p;

        const int tf = t + SCP - 1;
        if (tf < TT) fill(tf); else CP_COMMIT();
        CP_WAIT(SCP - 2);
        __syncthreads();

        const float* pp = part + ((t & 1) << 4);
        float4 q0 = *(const float4*)(pp);
        float4 q1 = *(const float4*)(pp + 4);
        float4 q2 = *(const float4*)(pp + 8);
        float4 q3 = *(const float4*)(pp + 12);
        float q = ((q0.x + q0.y) + (q0.z + q0.w)) + ((q1.x + q1.y) + (q1.z + q1.w))
                + ((q2.x + q2.y) + (q2.z + q2.w)) + ((q3.x + q3.y) + (q3.z + q3.w));

        const float s2 = q * svs[t];
        h.x = lt.x * (h.x - s2 * vt.x) + (1.0f - lt.x) * xt.x;
        h.y = lt.y * (h.y - s2 * vt.y) + (1.0f - lt.y) * xt.y;
        h.z = lt.z * (h.z - s2 * vt.z) + (1.0f - lt.z) * xt.z;
        h.w = lt.w * (h.w - s2 * vt.w) + (1.0f - lt.w) * xt.w;

        uint32_t h0, l0, h1, l1;
        split2(zt.x * h.x, zt.y * h.y, h0, l0);
        split2(zt.z * h.z, zt.w * h.w, h1, l1);
        const size_t og = (size_t)t * DI + c0;
        *(uint2*)(ghb + og) = make_uint2(h0, h1);
        *(uint2*)(glb + og) = make_uint2(l0, l1);
    }
}

// ---------------- launcher ----------------------------------------------------------
extern "C" void kernel_launch(void* const* d_in, const int* in_sizes, int n_in,
                              void* d_out, int out_size)
{
    const float* x     = (const float*)d_in[0];
    const float* omega = (const float*)d_in[1];
    const float* Win   = (const float*)d_in[2];
    const float* Wl    = (const float*)d_in[3];
    const float* bl    = (const float*)d_in[4];
    const float* Wv    = (const float*)d_in[5];
    const float* bv    = (const float*)d_in[6];
    const float* Wout  = (const float*)d_in[7];
    float* out = (float*)d_out;

    __nv_bfloat16 *xh, *xl, *winh, *winl, *wlh, *wll, *wvh, *wvl, *woh, *wol;
    __nv_bfloat16 *xih, *xil, *gh, *gl;
    float *xi, *szp, *lam, *v, *fcol;
    cudaGetSymbolAddress((void**)&xh,   g_xh);   cudaGetSymbolAddress((void**)&xl,   g_xl);
    cudaGetSymbolAddress((void**)&winh, g_winh); cudaGetSymbolAddress((void**)&winl, g_winl);
    cudaGetSymbolAddress((void**)&wlh,  g_wlh);  cudaGetSymbolAddress((void**)&wll,  g_wll);
    cudaGetSymbolAddress((void**)&wvh,  g_wvh);  cudaGetSymbolAddress((void**)&wvl,  g_wvl);
    cudaGetSymbolAddress((void**)&woh,  g_woh);  cudaGetSymbolAddress((void**)&wol,  g_wol);
    cudaGetSymbolAddress((void**)&xi,   g_xi);
    cudaGetSymbolAddress((void**)&xih,  g_xih);  cudaGetSymbolAddress((void**)&xil,  g_xil);
    cudaGetSymbolAddress((void**)&szp,  g_sz);
    cudaGetSymbolAddress((void**)&lam,  g_lam);  cudaGetSymbolAddress((void**)&v,    g_v);
    cudaGetSymbolAddress((void**)&gh,   g_gh);   cudaGetSymbolAddress((void**)&gl,   g_gl);
    cudaGetSymbolAddress((void**)&fcol, g_fcolA);

    cudaFuncSetAttribute(gemm_ps, cudaFuncAttributeMaxDynamicSharedMemorySize, GEMM_SMEM);
    cudaFuncSetAttribute(scan_kernel, cudaFuncAttributeMaxDynamicSharedMemorySize, SCAN_SMEM);

    // 0) all splits + fcol
    mega_pre<<<dim3((MROWS * DM) / 1024, 6), 256>>>(
        x, xh, xl, Win, winh, winl, Wl, wlh, wll, Wv, wvh, wvl, Wout, woh, wol,
        omega, fcol);

    // 1) GEMM1: xz -> xi (fp32 + split) | silu(z)
    gemm_ps<<<dim3(DX / 128, MROWS / 128, 1), 256, GEMM_SMEM>>>(
        xh, xl, DM, winh, winl, nullptr, nullptr, DM, DM,
        xi, nullptr, DI, nullptr, nullptr, fcol, xih, xil, szp, 2, 2);

    // 2) GEMM2+3 fused: z=0 -> lam, z=1 -> v
    gemm_ps<<<dim3(DI / 128, MROWS / 128, 2), 256, GEMM_SMEM>>>(
        xih, xil, DI, wlh, wll, wvh, wvl, DI, DI,
        lam, v, DI, bl, bv, fcol, nullptr, nullptr, nullptr, 1, 0);

    // 3) scan (profiled at ncu launch idx 3)
    scan_kernel<<<BB, SCT, SCAN_SMEM>>>(xi, szp, lam, v, gh, gl);

    // 4) GEMM4: out = g @ Wout^T
    gemm_ps<<<dim3(DM / 128, MROWS / 128, 1), 256, GEMM_SMEM>>>(
        gh, gl, DI, woh, wol, nullptr, nullptr, DI, DI,
        out, nullptr, DM, nullptr, nullptr, fcol, nullptr, nullptr, nullptr, 0, 0);
}